// round 9
// baseline (speedup 1.0000x reference)
#include <cuda_runtime.h>
#include <cstdint>
#include <cstddef>

// Problem constants
#define Bsz   32
#define Tlen  1024
#define Hdim  512
#define G4    2048                 // 4*H
#define Mrows (Tlen * Bsz)         // 32768
#define RTHREADS 256
#define NCHALF 64                  // CTAs per layer in pipeline kernel
#define RSH 40                     // smem row stride in floats (160 B)

// ---------------- static device scratch (no allocations allowed) -------------
__device__ float g_G  [(size_t)Mrows * G4];            // G0: [t*B+b][2048]
__device__ float g_G1 [(size_t)Tlen * G4 * Bsz];       // G1: [t][2048][32]
__device__ float g_hkb1[(size_t)Tlen * Hdim * Bsz];    // h1 in [t][k][b]
__device__ float g_hkb2[(size_t)Tlen * Hdim * Bsz];    // h2 in [t][k][b]
__device__ float g_h2 [(size_t)Mrows * Hdim];          // h2 seq [t*B+b][H]
__device__ int   g_cnt[3][Tlen];                       // cnt0 / cntp / cnt1

// ---------------- helpers ----------------------------------------------------
__device__ __forceinline__ float sigm_(float x) { return 1.0f / (1.0f + __expf(-x)); }
__device__ __forceinline__ float tanh_(float x) {
    float y;
    asm("tanh.approx.f32 %0, %1;" : "=f"(y) : "f"(x));
    return y;
}
__device__ __forceinline__ uint32_t f2tf32(float x) {
    uint32_t r;
    asm("cvt.rna.tf32.f32 %0, %1;" : "=r"(r) : "f"(x));
    return r;
}
__device__ __forceinline__ void mma_tf32(float* c, const uint32_t* a, const uint32_t* b) {
    asm volatile("mma.sync.aligned.m16n8k8.row.col.f32.tf32.tf32.f32 "
                 "{%0,%1,%2,%3}, {%4,%5,%6,%7}, {%8,%9}, {%0,%1,%2,%3};"
                 : "+f"(c[0]), "+f"(c[1]), "+f"(c[2]), "+f"(c[3])
                 : "r"(a[0]), "r"(a[1]), "r"(a[2]), "r"(a[3]), "r"(b[0]), "r"(b[1]));
}
__device__ __forceinline__ void warp_wait(volatile const int* p, int target, int lane) {
    if (lane == 0) { while (*p < target) {} }
    __syncwarp();
    asm volatile("" ::: "memory");
}

// ---------------- counter reset (graph-replay safe) --------------------------
__global__ void zero_cnt_kernel() {
    int i = blockIdx.x * blockDim.x + threadIdx.x;
    if (i < 3 * Tlen) ((int*)g_cnt)[i] = 0;
}

// =============================================================================
// tf32 mma.sync 3-pass split GEMM (UNCHANGED from round-7/8 passing kernel)
// =============================================================================
#define TM 128
#define TN 128
#define KS 32
#define RST 36
#define MAT_F (128 * RST)
#define BUF_F (2 * MAT_F)
#define OFF_A 0
#define OFF_W MAT_F
#define BUF_BYTES (BUF_F * 4)

__global__ __launch_bounds__(256, 1) void gemm_tf32(
    const float* __restrict__ A, const float* __restrict__ W,
    const float* __restrict__ b1, const float* __restrict__ b2,
    float* __restrict__ C, int Ntot, int amode, int cmode)
{
    extern __shared__ float smf[];

    const int tid  = threadIdx.x;
    const int wid  = tid >> 5;
    const int lane = tid & 31;
    const int bm = blockIdx.y * TM;
    const int bn = blockIdx.x * TN;
    const int wm = (wid & 3) * 32;
    const int wn = (wid >> 2) * 64;
    const int g  = lane >> 2;
    const int cfrag = lane & 3;

    const int rr  = tid >> 1;
    const int cc0 = (tid & 1) * 16;
    size_t arow;
    {
        int m = bm + rr;
        arow = amode ? (size_t)m * Hdim
                     : ((size_t)(m & 31) * Tlen + (size_t)(m >> 5)) * Hdim;
    }
    const float* ap = A + arow;
    const float* wp = W + (size_t)(bn + rr) * Hdim;
    const int sts = rr * RST + cc0;

    float acc[2][8][4];
#pragma unroll
    for (int i = 0; i < 2; i++)
#pragma unroll
        for (int j = 0; j < 8; j++)
#pragma unroll
            for (int q = 0; q < 4; q++) acc[i][j][q] = 0.0f;

    float4 pa[4], pw[4];
#pragma unroll
    for (int i = 0; i < 4; i++) {
        pa[i] = __ldg((const float4*)(ap + cc0 + i * 4));
        pw[i] = __ldg((const float4*)(wp + cc0 + i * 4));
    }

    const int NSTG = Hdim / KS;
    for (int kt = 0; kt < NSTG; kt++) {
        float* buf = smf + (kt & 1) * BUF_F;
#pragma unroll
        for (int i = 0; i < 4; i++) {
            *(float4*)&buf[OFF_A + sts + i * 4] = pa[i];
            *(float4*)&buf[OFF_W + sts + i * 4] = pw[i];
        }
        __syncthreads();

        if (kt + 1 < NSTG) {
            int kb = (kt + 1) * KS + cc0;
#pragma unroll
            for (int i = 0; i < 4; i++) {
                pa[i] = __ldg((const float4*)(ap + kb + i * 4));
                pw[i] = __ldg((const float4*)(wp + kb + i * 4));
            }
        }

        const float* As = buf + OFF_A;
        const float* Ws = buf + OFF_W;
#pragma unroll
        for (int ks = 0; ks < 4; ks++) {
            const int kof = ks * 8 + cfrag;
            uint32_t ah[2][4], am[2][4];
#pragma unroll
            for (int j = 0; j < 2; j++) {
                int ra = (wm + j * 16 + g) * RST + kof;
                float v0 = As[ra];
                float v1 = As[ra + 8 * RST];
                float v2 = As[ra + 4];
                float v3 = As[ra + 8 * RST + 4];
                ah[j][0] = f2tf32(v0); am[j][0] = f2tf32(v0 - __uint_as_float(ah[j][0]));
                ah[j][1] = f2tf32(v1); am[j][1] = f2tf32(v1 - __uint_as_float(ah[j][1]));
                ah[j][2] = f2tf32(v2); am[j][2] = f2tf32(v2 - __uint_as_float(ah[j][2]));
                ah[j][3] = f2tf32(v3); am[j][3] = f2tf32(v3 - __uint_as_float(ah[j][3]));
            }
            uint32_t bh[8][2], bmid[8][2];
#pragma unroll
            for (int n = 0; n < 8; n++) {
                int rb = (wn + n * 8 + g) * RST + kof;
                float v0 = Ws[rb];
                float v1 = Ws[rb + 4];
                bh[n][0] = f2tf32(v0); bmid[n][0] = f2tf32(v0 - __uint_as_float(bh[n][0]));
                bh[n][1] = f2tf32(v1); bmid[n][1] = f2tf32(v1 - __uint_as_float(bh[n][1]));
            }
#pragma unroll
            for (int j = 0; j < 2; j++)
#pragma unroll
                for (int n = 0; n < 8; n++) {
                    mma_tf32(acc[j][n], ah[j], bh[n]);
                    mma_tf32(acc[j][n], ah[j], bmid[n]);
                    mma_tf32(acc[j][n], am[j], bh[n]);
                }
        }
        __syncthreads();
    }

    const int cr = g;
    const int cn = cfrag * 2;
#pragma unroll
    for (int n = 0; n < 8; n++) {
        int ncol = bn + wn + n * 8 + cn;
        float bx = __ldg(b1 + ncol)     + (b2 ? __ldg(b2 + ncol)     : 0.0f);
        float by = __ldg(b1 + ncol + 1) + (b2 ? __ldg(b2 + ncol + 1) : 0.0f);
#pragma unroll
        for (int j = 0; j < 2; j++) {
            int m0 = bm + wm + j * 16 + cr;
#pragma unroll
            for (int h = 0; h < 2; h++) {
                int m = m0 + h * 8;
                size_t crow = cmode
                    ? ((size_t)(m & 31) * Tlen + (size_t)(m >> 5)) * (size_t)Ntot
                    : (size_t)m * Ntot;
                float2 v;
                v.x = acc[j][n][h * 2 + 0] + bx;
                v.y = acc[j][n][h * 2 + 1] + by;
                *(float2*)&C[crow + ncol] = v;
            }
        }
    }
}

// =============================================================================
// pipelined 2-layer recurrence. Grid = 128 CTAs:
//   CTA 0..63  : layer 0. Owns h-dims [8c, 8c+8) -> 32 gate rows. Per step t:
//                rec (h1(t) from h1(t-1), G0[t]) publish cnt0[t]; then proj
//                slice G1[t-1] rows [32c,32c+32) = h1(t-1) @ Wih1^T + bias,
//                publish cntp[t-1]. h1(t-1) staged once, reused for both.
//   CTA 64..127: layer 1. Waits cntp[t] (G1[t]) and cnt1[t-1] (h2 bcast),
//                rec step identical machinery, publishes cnt1[t] + h2 seq.
// Warp layout: w = tid>>5; mw = w&1 (m16 tile), kc = w>>2? NO: kc = w>>1 (k-chunk
// of 128). W fp32 in regs, tf32 hi/mid split on the fly (3-pass).
// =============================================================================
__device__ __forceinline__ void stage_chunk(const float* __restrict__ hstep,
                                            float* __restrict__ hsh,
                                            int kc, int mw, int lane)
{
    const int rbase = kc * 128 + mw * 64;
    const float4* src = (const float4*)(hstep + rbase * Bsz);
#pragma unroll
    for (int r = 0; r < 16; r++) {
        int f = lane + r * 32;
        float4 v = __ldcg(src + f);
        int k = f >> 3, bg = f & 7;
        *(float4*)&hsh[(rbase + k) * RSH + bg * 4] = v;
    }
}

__device__ __forceinline__ void mma_block(const float wreg[16][4],
                                          const float* __restrict__ hsh,
                                          float* __restrict__ red,
                                          int kc, int mw, int g, int cf)
{
    float acc[4][4];
#pragma unroll
    for (int nt = 0; nt < 4; nt++)
#pragma unroll
        for (int q = 0; q < 4; q++) acc[nt][q] = 0.0f;

#pragma unroll
    for (int s = 0; s < 16; s++) {
        const int krow = kc * 128 + s * 8;
        uint32_t ah[4], am[4];
#pragma unroll
        for (int q = 0; q < 4; q++) {
            ah[q] = f2tf32(wreg[s][q]);
            am[q] = f2tf32(wreg[s][q] - __uint_as_float(ah[q]));
        }
#pragma unroll
        for (int nt = 0; nt < 4; nt++) {
            float v0 = hsh[(krow + cf) * RSH + nt * 8 + g];
            float v1 = hsh[(krow + cf + 4) * RSH + nt * 8 + g];
            uint32_t hh[2], hm[2];
            hh[0] = f2tf32(v0); hm[0] = f2tf32(v0 - __uint_as_float(hh[0]));
            hh[1] = f2tf32(v1); hm[1] = f2tf32(v1 - __uint_as_float(hh[1]));
            mma_tf32(acc[nt], ah, hh);
            mma_tf32(acc[nt], ah, hm);
            mma_tf32(acc[nt], am, hh);
        }
    }
    float* rp = red + (size_t)kc * 32 * RSH + (size_t)(16 * mw) * RSH;
#pragma unroll
    for (int nt = 0; nt < 4; nt++) {
        int bc = nt * 8 + cf * 2;
        *(float2*)&rp[g * RSH + bc]       = make_float2(acc[nt][0], acc[nt][1]);
        *(float2*)&rp[(g + 8) * RSH + bc] = make_float2(acc[nt][2], acc[nt][3]);
    }
}

__global__ __launch_bounds__(RTHREADS) void lstm_pipe(
    const float* __restrict__ G0,   const float* __restrict__ Whh0,
    const float* __restrict__ Wih1, const float* __restrict__ Whh1,
    const float* __restrict__ bi1,  const float* __restrict__ bh1,
    float* __restrict__ G1,
    float* __restrict__ hkb1, float* __restrict__ hkb2,
    float* __restrict__ hseq2,
    int* __restrict__ cnt0, int* __restrict__ cntp, int* __restrict__ cnt1)
{
    extern __shared__ float sm[];
    float* hsh = sm;                      // [512][RSH]
    float* red = sm + 512 * RSH;          // [4][32][RSH]
    float* csh = red + 4 * 32 * RSH;      // [256]

    const int tid  = threadIdx.x;
    const int lane = tid & 31;
    const int w    = tid >> 5;
    const int mw   = w & 1;
    const int kc   = w >> 1;
    const int g    = lane >> 2;
    const int cf   = lane & 3;
    const int dd   = tid >> 5;            // activation role (all 256)
    const int b    = tid & 31;

    const bool isL0 = (blockIdx.x < NCHALF);
    const int  c    = isL0 ? blockIdx.x : blockIdx.x - NCHALF;
    const int  d0   = c * 8;

    // ---- load recurrent W (fp32) into regs --------------------------------
    const float* Wrec = isL0 ? Whh0 : Whh1;
    float wr[16][4];
    {
        const int j0 = 16 * mw + g, j1 = j0 + 8;
        const float* r0 = Wrec + ((size_t)(j0 >> 3) * Hdim + d0 + (j0 & 7)) * Hdim;
        const float* r1 = Wrec + ((size_t)(j1 >> 3) * Hdim + d0 + (j1 & 7)) * Hdim;
#pragma unroll
        for (int s = 0; s < 16; s++) {
            int k = kc * 128 + s * 8 + cf;
            wr[s][0] = __ldg(r0 + k);
            wr[s][1] = __ldg(r1 + k);
            wr[s][2] = __ldg(r0 + k + 4);
            wr[s][3] = __ldg(r1 + k + 4);
        }
    }
    // ---- L0 also loads its G1-projection W slice + bias -------------------
    float wp[16][4];
    float pb = 0.0f;
    if (isL0) {
        const int p0 = c * 32 + 16 * mw + g, p1 = p0 + 8;
        const float* q0 = Wih1 + (size_t)p0 * Hdim;
        const float* q1 = Wih1 + (size_t)p1 * Hdim;
#pragma unroll
        for (int s = 0; s < 16; s++) {
            int k = kc * 128 + s * 8 + cf;
            wp[s][0] = __ldg(q0 + k);
            wp[s][1] = __ldg(q1 + k);
            wp[s][2] = __ldg(q0 + k + 4);
            wp[s][3] = __ldg(q1 + k + 4);
        }
        int prow = c * 32 + (tid >> 3);
        pb = __ldg(bi1 + prow) + __ldg(bh1 + prow);
    }
    csh[tid] = 0.0f;
    __syncthreads();

    if (isL0) {
        // =================== layer 0 + G1 projection =======================
        for (int t = 0; t <= Tlen; t++) {
            float gp0 = 0.f, gp1 = 0.f, gp2 = 0.f, gp3 = 0.f;
            if (t < Tlen) {  // prefetch G0[t] (independent of waits)
                const float* gb = G0 + ((size_t)t * Bsz + b) * G4 + d0 + dd;
                gp0 = __ldg(gb);
                gp1 = __ldg(gb + Hdim);
                gp2 = __ldg(gb + 2 * Hdim);
                gp3 = __ldg(gb + 3 * Hdim);
            }
            if (t > 0) {
                warp_wait(cnt0 + t - 1, NCHALF, lane);
                stage_chunk(hkb1 + (size_t)(t - 1) * Hdim * Bsz, hsh, kc, mw, lane);
                __syncthreads();
                if (t < Tlen) {
                    mma_block(wr, hsh, red, kc, mw, g, cf);
                    __syncthreads();
                }
            }
            if (t < Tlen) {
                // activations
                float s0 = gp0, s1 = gp1, s2 = gp2, s3 = gp3;
                if (t > 0) {
#pragma unroll
                    for (int q = 0; q < 4; q++) {
                        const float* rw = red + (size_t)q * 32 * RSH;
                        s0 += rw[(0 * 8 + dd) * RSH + b];
                        s1 += rw[(1 * 8 + dd) * RSH + b];
                        s2 += rw[(2 * 8 + dd) * RSH + b];
                        s3 += rw[(3 * 8 + dd) * RSH + b];
                    }
                }
                float ig = sigm_(s0), fg = sigm_(s1);
                float gg = tanh_(s2), og = sigm_(s3);
                float cv = fg * csh[tid] + ig * gg;
                csh[tid] = cv;
                float hv = og * tanh_(cv);
                hkb1[(size_t)t * Hdim * Bsz + (size_t)(d0 + dd) * Bsz + b] = hv;
                __threadfence();
                __syncthreads();
                if (tid == 0) atomicAdd(&cnt0[t], 1);
            }
            if (t > 0) {
                // G1[t-1] projection from staged h1(t-1)
                mma_block(wp, hsh, red, kc, mw, g, cf);
                __syncthreads();
                {
                    int prow = tid >> 3, bg = tid & 7;
                    float4 sv = *(const float4*)&red[prow * RSH + bg * 4];
#pragma unroll
                    for (int q = 1; q < 4; q++) {
                        float4 v = *(const float4*)&red[(size_t)q * 32 * RSH + prow * RSH + bg * 4];
                        sv.x += v.x; sv.y += v.y; sv.z += v.z; sv.w += v.w;
                    }
                    sv.x += pb; sv.y += pb; sv.z += pb; sv.w += pb;
                    *(float4*)&G1[((size_t)(t - 1) * G4 + c * 32 + prow) * Bsz + bg * 4] = sv;
                }
                __threadfence();
                __syncthreads();
                if (tid == 0) atomicAdd(&cntp[t - 1], 1);
            }
        }
    } else {
        // =================== layer 1 ======================================
        for (int t = 0; t < Tlen; t++) {
            warp_wait(cntp + t, NCHALF, lane);
            // gates for this step (G1 layout [t][2048][32])
            const float* gb = G1 + ((size_t)t * G4 + d0 + dd) * Bsz + b;
            float gp0 = __ldg(gb);
            float gp1 = __ldg(gb + (size_t)Hdim * Bsz);
            float gp2 = __ldg(gb + (size_t)2 * Hdim * Bsz);
            float gp3 = __ldg(gb + (size_t)3 * Hdim * Bsz);
            if (t > 0) {
                warp_wait(cnt1 + t - 1, NCHALF, lane);
                stage_chunk(hkb2 + (size_t)(t - 1) * Hdim * Bsz, hsh, kc, mw, lane);
                __syncthreads();
                mma_block(wr, hsh, red, kc, mw, g, cf);
            }
            __syncthreads();
            {
                float s0 = gp0, s1 = gp1, s2 = gp2, s3 = gp3;
                if (t > 0) {
#pragma unroll
                    for (int q = 0; q < 4; q++) {
                        const float* rw = red + (size_t)q * 32 * RSH;
                        s0 += rw[(0 * 8 + dd) * RSH + b];
                        s1 += rw[(1 * 8 + dd) * RSH + b];
                        s2 += rw[(2 * 8 + dd) * RSH + b];
                        s3 += rw[(3 * 8 + dd) * RSH + b];
                    }
                }
                float ig = sigm_(s0), fg = sigm_(s1);
                float gg = tanh_(s2), og = sigm_(s3);
                float cv = fg * csh[tid] + ig * gg;
                csh[tid] = cv;
                float hv = og * tanh_(cv);
                hkb2[(size_t)t * Hdim * Bsz + (size_t)(d0 + dd) * Bsz + b] = hv;
                hseq2[((size_t)t * Bsz + b) * Hdim + d0 + dd] = hv;
            }
            __threadfence();
            __syncthreads();
            if (tid == 0) atomicAdd(&cnt1[t], 1);
        }
    }
}

// ---------------- launcher ---------------------------------------------------
extern "C" void kernel_launch(void* const* d_in, const int* in_sizes, int n_in,
                              void* d_out, int out_size)
{
    (void)in_sizes; (void)n_in; (void)out_size;
    const float* x     = (const float*)d_in[0];
    const float* W_ih  = (const float*)d_in[1];   // [2][2048][512]
    const float* W_hh  = (const float*)d_in[2];   // [2][2048][512]
    const float* b_ih  = (const float*)d_in[3];   // [2][2048]
    const float* b_hh  = (const float*)d_in[4];   // [2][2048]
    const float* W_out = (const float*)d_in[5];   // [512][512]
    const float* b_out = (const float*)d_in[6];   // [512]
    float* out = (float*)d_out;

    float *G0, *G1, *hkb1, *hkb2, *h2; int* cnt;
    cudaGetSymbolAddress((void**)&G0,   g_G);
    cudaGetSymbolAddress((void**)&G1,   g_G1);
    cudaGetSymbolAddress((void**)&hkb1, g_hkb1);
    cudaGetSymbolAddress((void**)&hkb2, g_hkb2);
    cudaGetSymbolAddress((void**)&h2,   g_h2);
    cudaGetSymbolAddress((void**)&cnt,  g_cnt);

    const size_t wl = (size_t)G4 * Hdim;                     // per-layer W stride
    const int pipe_smem = (512 * RSH + 4 * 32 * RSH + 256) * 4;   // 103424 B
    const int gemm_smem = 2 * BUF_BYTES;                          // 73728 B
    cudaFuncSetAttribute(lstm_pipe, cudaFuncAttributeMaxDynamicSharedMemorySize, pipe_smem);
    cudaFuncSetAttribute(gemm_tf32, cudaFuncAttributeMaxDynamicSharedMemorySize, gemm_smem);

    zero_cnt_kernel<<<12, 256>>>();

    // layer-0 input projection: G0 = x @ Wih0^T + b_ih0 + b_hh0
    gemm_tf32<<<dim3(G4 / TN, Mrows / TM), 256, gemm_smem>>>(
        x, W_ih, b_ih, b_hh, G0, G4, /*amode=*/0, /*cmode=*/0);

    // pipelined 2-layer recurrence (includes layer-1 input projection)
    lstm_pipe<<<2 * NCHALF, RTHREADS, pipe_smem>>>(
        G0, W_hh, W_ih + wl, W_hh + wl,
        b_ih + G4, b_hh + G4,
        G1, hkb1, hkb2, h2,
        cnt, cnt + Tlen, cnt + 2 * Tlen);

    // output projection -> [B,T,H]
    gemm_tf32<<<dim3(Hdim / TN, Mrows / TM), 256, gemm_smem>>>(
        h2, W_out, b_out, nullptr, out, Hdim, /*amode=*/1, /*cmode=*/1);
}

// round 11
// speedup vs baseline: 1.0152x; 1.0152x over previous
#include <cuda_runtime.h>
#include <cstdint>
#include <cstddef>

// Problem constants
#define Bsz   32
#define Tlen  1024
#define Hdim  512
#define G4    2048                 // 4*H
#define Mrows (Tlen * Bsz)         // 32768
#define RTHREADS 256
#define NCTA2 64                   // recurrent CTAs (8 h-dims each)
#define RSH 40                     // smem row stride in floats (160 B)

// ---------------- static device scratch (no allocations allowed) -------------
__device__ float g_G  [(size_t)Mrows * G4];          // gate pre-acts [t*B+b][2048]
__device__ float g_h1 [(size_t)Mrows * Hdim];        // h1 seq [t*B+b][H]
__device__ float g_h2 [(size_t)Mrows * Hdim];        // h2 seq [t*B+b][H]
__device__ float g_hkb1[(size_t)Tlen * Hdim * Bsz];  // h1 [t][k][b]
__device__ float g_hkb2[(size_t)Tlen * Hdim * Bsz];  // h2 [t][k][b]
__device__ int   g_flag[2][Tlen][NCTA2];             // per-CTA done flags

// ---------------- helpers ----------------------------------------------------
__device__ __forceinline__ float sigm_(float x) { return 1.0f / (1.0f + __expf(-x)); }
__device__ __forceinline__ float tanh_(float x) {
    float y;
    asm("tanh.approx.f32 %0, %1;" : "=f"(y) : "f"(x));
    return y;
}
__device__ __forceinline__ uint32_t f2tf32(float x) {
    uint32_t r;
    asm("cvt.rna.tf32.f32 %0, %1;" : "=r"(r) : "f"(x));
    return r;
}
__device__ __forceinline__ void mma_tf32(float* c, const uint32_t* a, const uint32_t* b) {
    asm volatile("mma.sync.aligned.m16n8k8.row.col.f32.tf32.tf32.f32 "
                 "{%0,%1,%2,%3}, {%4,%5,%6,%7}, {%8,%9}, {%0,%1,%2,%3};"
                 : "+f"(c[0]), "+f"(c[1]), "+f"(c[2]), "+f"(c[3])
                 : "r"(a[0]), "r"(a[1]), "r"(a[2]), "r"(a[3]), "r"(b[0]), "r"(b[1]));
}

// ---------------- flag reset (graph-replay safe) ------------------------------
__global__ void zero_flag_kernel() {
    int i = blockIdx.x * blockDim.x + threadIdx.x;
    if (i < 2 * Tlen * NCTA2) ((int*)g_flag)[i] = 0;
}

// =============================================================================
// tf32 mma.sync 3-pass split GEMM (UNCHANGED from round-7/8 passing kernel)
// =============================================================================
#define TM 128
#define TN 128
#define KS 32
#define RST 36
#define MAT_F (128 * RST)
#define BUF_F (2 * MAT_F)
#define OFF_A 0
#define OFF_W MAT_F
#define BUF_BYTES (BUF_F * 4)

__global__ __launch_bounds__(256, 1) void gemm_tf32(
    const float* __restrict__ A, const float* __restrict__ W,
    const float* __restrict__ b1, const float* __restrict__ b2,
    float* __restrict__ C, int Ntot, int amode, int cmode)
{
    extern __shared__ float smf[];

    const int tid  = threadIdx.x;
    const int wid  = tid >> 5;
    const int lane = tid & 31;
    const int bm = blockIdx.y * TM;
    const int bn = blockIdx.x * TN;
    const int wm = (wid & 3) * 32;
    const int wn = (wid >> 2) * 64;
    const int g  = lane >> 2;
    const int cfrag = lane & 3;

    const int rr  = tid >> 1;
    const int cc0 = (tid & 1) * 16;
    size_t arow;
    {
        int m = bm + rr;
        arow = amode ? (size_t)m * Hdim
                     : ((size_t)(m & 31) * Tlen + (size_t)(m >> 5)) * Hdim;
    }
    const float* ap = A + arow;
    const float* wp = W + (size_t)(bn + rr) * Hdim;
    const int sts = rr * RST + cc0;

    float acc[2][8][4];
#pragma unroll
    for (int i = 0; i < 2; i++)
#pragma unroll
        for (int j = 0; j < 8; j++)
#pragma unroll
            for (int q = 0; q < 4; q++) acc[i][j][q] = 0.0f;

    float4 pa[4], pw[4];
#pragma unroll
    for (int i = 0; i < 4; i++) {
        pa[i] = __ldg((const float4*)(ap + cc0 + i * 4));
        pw[i] = __ldg((const float4*)(wp + cc0 + i * 4));
    }

    const int NSTG = Hdim / KS;
    for (int kt = 0; kt < NSTG; kt++) {
        float* buf = smf + (kt & 1) * BUF_F;
#pragma unroll
        for (int i = 0; i < 4; i++) {
            *(float4*)&buf[OFF_A + sts + i * 4] = pa[i];
            *(float4*)&buf[OFF_W + sts + i * 4] = pw[i];
        }
        __syncthreads();

        if (kt + 1 < NSTG) {
            int kb = (kt + 1) * KS + cc0;
#pragma unroll
            for (int i = 0; i < 4; i++) {
                pa[i] = __ldg((const float4*)(ap + kb + i * 4));
                pw[i] = __ldg((const float4*)(wp + kb + i * 4));
            }
        }

        const float* As = buf + OFF_A;
        const float* Ws = buf + OFF_W;
#pragma unroll
        for (int ks = 0; ks < 4; ks++) {
            const int kof = ks * 8 + cfrag;
            uint32_t ah[2][4], am[2][4];
#pragma unroll
            for (int j = 0; j < 2; j++) {
                int ra = (wm + j * 16 + g) * RST + kof;
                float v0 = As[ra];
                float v1 = As[ra + 8 * RST];
                float v2 = As[ra + 4];
                float v3 = As[ra + 8 * RST + 4];
                ah[j][0] = f2tf32(v0); am[j][0] = f2tf32(v0 - __uint_as_float(ah[j][0]));
                ah[j][1] = f2tf32(v1); am[j][1] = f2tf32(v1 - __uint_as_float(ah[j][1]));
                ah[j][2] = f2tf32(v2); am[j][2] = f2tf32(v2 - __uint_as_float(ah[j][2]));
                ah[j][3] = f2tf32(v3); am[j][3] = f2tf32(v3 - __uint_as_float(ah[j][3]));
            }
            uint32_t bh[8][2], bmid[8][2];
#pragma unroll
            for (int n = 0; n < 8; n++) {
                int rb = (wn + n * 8 + g) * RST + kof;
                float v0 = Ws[rb];
                float v1 = Ws[rb + 4];
                bh[n][0] = f2tf32(v0); bmid[n][0] = f2tf32(v0 - __uint_as_float(bh[n][0]));
                bh[n][1] = f2tf32(v1); bmid[n][1] = f2tf32(v1 - __uint_as_float(bh[n][1]));
            }
#pragma unroll
            for (int j = 0; j < 2; j++)
#pragma unroll
                for (int n = 0; n < 8; n++) {
                    mma_tf32(acc[j][n], ah[j], bh[n]);
                    mma_tf32(acc[j][n], ah[j], bmid[n]);
                    mma_tf32(acc[j][n], am[j], bh[n]);
                }
        }
        __syncthreads();
    }

    const int cr = g;
    const int cn = cfrag * 2;
#pragma unroll
    for (int n = 0; n < 8; n++) {
        int ncol = bn + wn + n * 8 + cn;
        float bx = __ldg(b1 + ncol)     + (b2 ? __ldg(b2 + ncol)     : 0.0f);
        float by = __ldg(b1 + ncol + 1) + (b2 ? __ldg(b2 + ncol + 1) : 0.0f);
#pragma unroll
        for (int j = 0; j < 2; j++) {
            int m0 = bm + wm + j * 16 + cr;
#pragma unroll
            for (int h = 0; h < 2; h++) {
                int m = m0 + h * 8;
                size_t crow = cmode
                    ? ((size_t)(m & 31) * Tlen + (size_t)(m >> 5)) * (size_t)Ntot
                    : (size_t)m * Ntot;
                float2 v;
                v.x = acc[j][n][h * 2 + 0] + bx;
                v.y = acc[j][n][h * 2 + 1] + by;
                *(float2*)&C[crow + ncol] = v;
            }
        }
    }
}

// =============================================================================
// recurrent kernel v3 — 64 CTAs, 8 h-dims each (32 gate rows), fine-grained
// per-warp producer waits using ONLY proven sync primitives:
//   wait    = volatile loads (R2/R8/R9-proven spin idiom)
//   publish = __threadfence() + __syncthreads() + tid0 volatile store
// mma/staging blocks verbatim from round-9 L1 path (PASSED, rel_err 7.5e-6).
// =============================================================================
__device__ __forceinline__ void stage_chunk(const float* __restrict__ hstep,
                                            float* __restrict__ hsh,
                                            int kc, int mw, int lane)
{
    const int rbase = kc * 128 + mw * 64;
    const float4* src = (const float4*)(hstep + rbase * Bsz);
#pragma unroll
    for (int r = 0; r < 16; r++) {
        int f = lane + r * 32;
        float4 v = __ldcg(src + f);
        int k = f >> 3, bg = f & 7;
        *(float4*)&hsh[(rbase + k) * RSH + bg * 4] = v;
    }
}

__device__ __forceinline__ void mma_block(const float wreg[16][4],
                                          const float* __restrict__ hsh,
                                          float* __restrict__ red,
                                          int kc, int mw, int g, int cf)
{
    float acc[4][4];
#pragma unroll
    for (int nt = 0; nt < 4; nt++)
#pragma unroll
        for (int q = 0; q < 4; q++) acc[nt][q] = 0.0f;

#pragma unroll
    for (int s = 0; s < 16; s++) {
        const int krow = kc * 128 + s * 8;
        uint32_t ah[4], am[4];
#pragma unroll
        for (int q = 0; q < 4; q++) {
            ah[q] = f2tf32(wreg[s][q]);
            am[q] = f2tf32(wreg[s][q] - __uint_as_float(ah[q]));
        }
#pragma unroll
        for (int nt = 0; nt < 4; nt++) {
            float v0 = hsh[(krow + cf) * RSH + nt * 8 + g];
            float v1 = hsh[(krow + cf + 4) * RSH + nt * 8 + g];
            uint32_t hh[2], hm[2];
            hh[0] = f2tf32(v0); hm[0] = f2tf32(v0 - __uint_as_float(hh[0]));
            hh[1] = f2tf32(v1); hm[1] = f2tf32(v1 - __uint_as_float(hh[1]));
            mma_tf32(acc[nt], ah, hh);
            mma_tf32(acc[nt], ah, hm);
            mma_tf32(acc[nt], am, hh);
        }
    }
    float* rp = red + (size_t)kc * 32 * RSH + (size_t)(16 * mw) * RSH;
#pragma unroll
    for (int nt = 0; nt < 4; nt++) {
        int bc = nt * 8 + cf * 2;
        *(float2*)&rp[g * RSH + bc]       = make_float2(acc[nt][0], acc[nt][1]);
        *(float2*)&rp[(g + 8) * RSH + bc] = make_float2(acc[nt][2], acc[nt][3]);
    }
}

__global__ __launch_bounds__(RTHREADS) void lstm_rec3(
    const float* __restrict__ G, const float* __restrict__ Wh,
    float* __restrict__ hkb, float* __restrict__ hseq,
    int* __restrict__ flags)          // [Tlen][NCTA2] for this layer
{
    extern __shared__ float sm[];
    float* hsh = sm;                      // [512][RSH]
    float* red = sm + 512 * RSH;          // [4][32][RSH]
    float* csh = red + 4 * 32 * RSH;      // [256]

    const int tid  = threadIdx.x;
    const int lane = tid & 31;
    const int w    = tid >> 5;
    const int mw   = w & 1;               // m16 tile 0/1
    const int kc   = w >> 1;              // k-chunk 0..3 (128 k each)
    const int g    = lane >> 2;
    const int cf   = lane & 3;
    const int dd   = tid >> 5;            // activation h-dim 0..7
    const int b    = tid & 31;
    const int c    = blockIdx.x;
    const int d0   = c * 8;

    // ---- load recurrent W (fp32) into regs (round-9 validated mapping) ----
    float wr[16][4];
    {
        const int j0 = 16 * mw + g, j1 = j0 + 8;
        const float* r0 = Wh + ((size_t)(j0 >> 3) * Hdim + d0 + (j0 & 7)) * Hdim;
        const float* r1 = Wh + ((size_t)(j1 >> 3) * Hdim + d0 + (j1 & 7)) * Hdim;
#pragma unroll
        for (int s = 0; s < 16; s++) {
            int k = kc * 128 + s * 8 + cf;
            wr[s][0] = __ldg(r0 + k);
            wr[s][1] = __ldg(r1 + k);
            wr[s][2] = __ldg(r0 + k + 4);
            wr[s][3] = __ldg(r1 + k + 4);
        }
    }
    csh[tid] = 0.0f;
    __syncthreads();

    for (int t = 0; t < Tlen; t++) {
        // prefetch this step's gate pre-activations (independent of waits)
        const float* gb = G + ((size_t)t * Bsz + b) * G4 + d0 + dd;
        float gp0 = __ldg(gb);
        float gp1 = __ldg(gb + Hdim);
        float gp2 = __ldg(gb + 2 * Hdim);
        float gp3 = __ldg(gb + 3 * Hdim);

        if (t > 0) {
            // wait ONLY for the 8 CTAs producing this warp's 64 h-dims
            // (volatile spin — the thrice-proven idiom)
            if (lane < 8) {
                volatile const int* fp =
                    flags + (size_t)(t - 1) * NCTA2 + kc * 16 + mw * 8 + lane;
                while (*fp == 0) {}
            }
            __syncwarp();
            stage_chunk(hkb + (size_t)(t - 1) * Hdim * Bsz, hsh, kc, mw, lane);
            __syncthreads();
            mma_block(wr, hsh, red, kc, mw, g, cf);
        }
        __syncthreads();

        // activation: one h value per thread (dim d0+dd, batch b)
        {
            float s0 = gp0, s1 = gp1, s2 = gp2, s3 = gp3;
            if (t > 0) {
#pragma unroll
                for (int q = 0; q < 4; q++) {
                    const float* rw = red + (size_t)q * 32 * RSH;
                    s0 += rw[(0 * 8 + dd) * RSH + b];
                    s1 += rw[(1 * 8 + dd) * RSH + b];
                    s2 += rw[(2 * 8 + dd) * RSH + b];
                    s3 += rw[(3 * 8 + dd) * RSH + b];
                }
            }
            float ig = sigm_(s0), fg = sigm_(s1);
            float gg = tanh_(s2), og = sigm_(s3);
            float cv = fg * csh[tid] + ig * gg;
            csh[tid] = cv;
            float hv = og * tanh_(cv);
            hkb[(size_t)t * Hdim * Bsz + (size_t)(d0 + dd) * Bsz + b] = hv;
            hseq[((size_t)t * Bsz + b) * Hdim + d0 + dd] = hv;
        }
        __threadfence();
        __syncthreads();
        // publish own flag (single writer -> plain volatile store after fence)
        if (tid == 0) {
            *((volatile int*)(flags + (size_t)t * NCTA2 + c)) = 1;
        }
    }
}

// ---------------- launcher ---------------------------------------------------
extern "C" void kernel_launch(void* const* d_in, const int* in_sizes, int n_in,
                              void* d_out, int out_size)
{
    (void)in_sizes; (void)n_in; (void)out_size;
    const float* x     = (const float*)d_in[0];
    const float* W_ih  = (const float*)d_in[1];   // [2][2048][512]
    const float* W_hh  = (const float*)d_in[2];   // [2][2048][512]
    const float* b_ih  = (const float*)d_in[3];   // [2][2048]
    const float* b_hh  = (const float*)d_in[4];   // [2][2048]
    const float* W_out = (const float*)d_in[5];   // [512][512]
    const float* b_out = (const float*)d_in[6];   // [512]
    float* out = (float*)d_out;

    float *G, *h1, *h2, *hkb1, *hkb2; int* flag;
    cudaGetSymbolAddress((void**)&G,    g_G);
    cudaGetSymbolAddress((void**)&h1,   g_h1);
    cudaGetSymbolAddress((void**)&h2,   g_h2);
    cudaGetSymbolAddress((void**)&hkb1, g_hkb1);
    cudaGetSymbolAddress((void**)&hkb2, g_hkb2);
    cudaGetSymbolAddress((void**)&flag, g_flag);

    const size_t wl = (size_t)G4 * Hdim;
    const int rec_smem  = (512 * RSH + 4 * 32 * RSH + 256) * 4;   // 103424 B
    const int gemm_smem = 2 * BUF_BYTES;                          // 73728 B
    cudaFuncSetAttribute(lstm_rec3, cudaFuncAttributeMaxDynamicSharedMemorySize, rec_smem);
    cudaFuncSetAttribute(gemm_tf32, cudaFuncAttributeMaxDynamicSharedMemorySize, gemm_smem);

    zero_flag_kernel<<<(2 * Tlen * NCTA2 + 255) / 256, 256>>>();

    // layer 0: G = x @ Wih0^T + b
    gemm_tf32<<<dim3(G4 / TN, Mrows / TM), 256, gemm_smem>>>(
        x, W_ih, b_ih, b_hh, G, G4, /*amode=*/0, /*cmode=*/0);
    lstm_rec3<<<NCTA2, RTHREADS, rec_smem>>>(G, W_hh, hkb1, h1, flag);

    // layer 1: G = h1 @ Wih1^T + b
    gemm_tf32<<<dim3(G4 / TN, Mrows / TM), 256, gemm_smem>>>(
        h1, W_ih + wl, b_ih + G4, b_hh + G4, G, G4, /*amode=*/1, /*cmode=*/0);
    lstm_rec3<<<NCTA2, RTHREADS, rec_smem>>>(G, W_hh + wl, hkb2, h2, flag + Tlen * NCTA2);

    // output projection -> [B,T,H]
    gemm_tf32<<<dim3(Hdim / TN, Mrows / TM), 256, gemm_smem>>>(
        h2, W_out, b_out, nullptr, out, Hdim, /*amode=*/1, /*cmode=*/1);
}

// round 14
// speedup vs baseline: 1.2910x; 1.2717x over previous
#include <cuda_runtime.h>
#include <cstdint>
#include <cstddef>

// Problem constants
#define Bsz   32
#define Tlen  1024
#define Hdim  512
#define G4    2048                 // 4*H
#define Mrows (Tlen * Bsz)         // 32768
#define NCTA  128                  // recurrent CTAs
#define RTHREADS 256
#define RSH 40                     // rec smem row stride in floats (160 B)

// ---------------- static device scratch (no allocations allowed) -------------
__device__ float g_G[(size_t)Mrows * G4];          // gate pre-activations [t*B+b][4H]
__device__ float g_h1[(size_t)Mrows * Hdim];       // layer-0 outputs [t*B+b][H]
__device__ float g_h2[(size_t)Mrows * Hdim];       // layer-1 outputs [t*B+b][H]
__device__ float g_hkb[(size_t)Tlen * Hdim * Bsz]; // h in [t][k][b] layout
__device__ int   g_cnt[2][Tlen];                   // per-step arrival counters

// ---------------- helpers ----------------------------------------------------
__device__ __forceinline__ float sigm_(float x) { return 1.0f / (1.0f + __expf(-x)); }
__device__ __forceinline__ float tanh_(float x) {
    float y;
    asm("tanh.approx.f32 %0, %1;" : "=f"(y) : "f"(x));
    return y;
}
__device__ __forceinline__ uint32_t f2tf32(float x) {
    uint32_t r;
    asm("cvt.rna.tf32.f32 %0, %1;" : "=r"(r) : "f"(x));
    return r;
}
__device__ __forceinline__ void mma_tf32(float* c, const uint32_t* a, const uint32_t* b) {
    asm volatile("mma.sync.aligned.m16n8k8.row.col.f32.tf32.tf32.f32 "
                 "{%0,%1,%2,%3}, {%4,%5,%6,%7}, {%8,%9}, {%0,%1,%2,%3};"
                 : "+f"(c[0]), "+f"(c[1]), "+f"(c[2]), "+f"(c[3])
                 : "r"(a[0]), "r"(a[1]), "r"(a[2]), "r"(a[3]), "r"(b[0]), "r"(b[1]));
}

// ---------------- counter reset (graph-replay safe) --------------------------
__global__ void zero_cnt_kernel() {
    int i = blockIdx.x * blockDim.x + threadIdx.x;
    if (i < 2 * Tlen) ((int*)g_cnt)[i] = 0;
}

// =============================================================================
// tf32 mma.sync 3-pass split GEMM v2:  C[m][n] = sum_k A[m][k]*W[n][k] + bias
// Same math as the round-7/8 passing kernel, but the hi/mid tf32 split is done
// ONCE at staging time (4 smem tiles: Ahi/Amid/Whi/Wmid) instead of at every
// fragment load. Compute loop = raw-bit LDS + mma only (no ALU).
// amode 0: A row m -> x[(m&31)*T + (m>>5)]   (x is [B,T,H])
// amode 1: A row m -> A[m]
// cmode 0: C row m -> C[m*Ntot]
// cmode 1: C row m -> C[((m&31)*T + (m>>5))*Ntot]
// =============================================================================
#define TM 128
#define TN 128
#define KS 32
#define RST 36                     // smem row stride in floats (144 B)
#define MAT_F (128 * RST)          // 4608 floats per tile
#define BUF_F (4 * MAT_F)          // Ahi + Amid + Whi + Wmid
#define OFF_AHI  0
#define OFF_AMID (1 * MAT_F)
#define OFF_WHI  (2 * MAT_F)
#define OFF_WMID (3 * MAT_F)
#define BUF_BYTES (BUF_F * 4)      // 73728 B per stage buffer

__global__ __launch_bounds__(256, 1) void gemm_tf32(
    const float* __restrict__ A, const float* __restrict__ W,
    const float* __restrict__ b1, const float* __restrict__ b2,
    float* __restrict__ C, int Ntot, int amode, int cmode)
{
    extern __shared__ float smf[];

    const int tid  = threadIdx.x;
    const int wid  = tid >> 5;
    const int lane = tid & 31;
    const int bm = blockIdx.y * TM;
    const int bn = blockIdx.x * TN;
    const int wm = (wid & 3) * 32;
    const int wn = (wid >> 2) * 64;
    const int g  = lane >> 2;
    const int cfrag = lane & 3;

    const int rr  = tid >> 1;
    const int cc0 = (tid & 1) * 16;
    size_t arow;
    {
        int m = bm + rr;
        arow = amode ? (size_t)m * Hdim
                     : ((size_t)(m & 31) * Tlen + (size_t)(m >> 5)) * Hdim;
    }
    const float* ap = A + arow;
    const float* wp = W + (size_t)(bn + rr) * Hdim;
    const int sts = rr * RST + cc0;

    float acc[2][8][4];
#pragma unroll
    for (int i = 0; i < 2; i++)
#pragma unroll
        for (int j = 0; j < 8; j++)
#pragma unroll
            for (int q = 0; q < 4; q++) acc[i][j][q] = 0.0f;

    float4 pa[4], pw[4];
#pragma unroll
    for (int i = 0; i < 4; i++) {
        pa[i] = __ldg((const float4*)(ap + cc0 + i * 4));
        pw[i] = __ldg((const float4*)(wp + cc0 + i * 4));
    }

    const int NSTG = Hdim / KS;  // 16
    for (int kt = 0; kt < NSTG; kt++) {
        float* buf = smf + (kt & 1) * BUF_F;
        // ---- stage with one-time hi/mid split ----
#pragma unroll
        for (int i = 0; i < 4; i++) {
            float4 v = pa[i];
            float4 hi, mid;
            hi.x = __uint_as_float(f2tf32(v.x)); mid.x = __uint_as_float(f2tf32(v.x - hi.x));
            hi.y = __uint_as_float(f2tf32(v.y)); mid.y = __uint_as_float(f2tf32(v.y - hi.y));
            hi.z = __uint_as_float(f2tf32(v.z)); mid.z = __uint_as_float(f2tf32(v.z - hi.z));
            hi.w = __uint_as_float(f2tf32(v.w)); mid.w = __uint_as_float(f2tf32(v.w - hi.w));
            *(float4*)&buf[OFF_AHI  + sts + i * 4] = hi;
            *(float4*)&buf[OFF_AMID + sts + i * 4] = mid;

            v = pw[i];
            hi.x = __uint_as_float(f2tf32(v.x)); mid.x = __uint_as_float(f2tf32(v.x - hi.x));
            hi.y = __uint_as_float(f2tf32(v.y)); mid.y = __uint_as_float(f2tf32(v.y - hi.y));
            hi.z = __uint_as_float(f2tf32(v.z)); mid.z = __uint_as_float(f2tf32(v.z - hi.z));
            hi.w = __uint_as_float(f2tf32(v.w)); mid.w = __uint_as_float(f2tf32(v.w - hi.w));
            *(float4*)&buf[OFF_WHI  + sts + i * 4] = hi;
            *(float4*)&buf[OFF_WMID + sts + i * 4] = mid;
        }
        __syncthreads();

        if (kt + 1 < NSTG) {
            int kb = (kt + 1) * KS + cc0;
#pragma unroll
            for (int i = 0; i < 4; i++) {
                pa[i] = __ldg((const float4*)(ap + kb + i * 4));
                pw[i] = __ldg((const float4*)(wp + kb + i * 4));
            }
        }

        const float* Ahi  = buf + OFF_AHI;
        const float* Amid = buf + OFF_AMID;
        const float* Whi  = buf + OFF_WHI;
        const float* Wmid = buf + OFF_WMID;
        // ---- compute: raw-bit fragment loads + mma only ----
#pragma unroll
        for (int ks = 0; ks < 4; ks++) {
            const int kof = ks * 8 + cfrag;
            uint32_t ah[2][4], am[2][4];
#pragma unroll
            for (int j = 0; j < 2; j++) {
                int ra = (wm + j * 16 + g) * RST + kof;
                ah[j][0] = __float_as_uint(Ahi[ra]);
                ah[j][1] = __float_as_uint(Ahi[ra + 8 * RST]);
                ah[j][2] = __float_as_uint(Ahi[ra + 4]);
                ah[j][3] = __float_as_uint(Ahi[ra + 8 * RST + 4]);
                am[j][0] = __float_as_uint(Amid[ra]);
                am[j][1] = __float_as_uint(Amid[ra + 8 * RST]);
                am[j][2] = __float_as_uint(Amid[ra + 4]);
                am[j][3] = __float_as_uint(Amid[ra + 8 * RST + 4]);
            }
            uint32_t bh[8][2], bmid[8][2];
#pragma unroll
            for (int n = 0; n < 8; n++) {
                int rb = (wn + n * 8 + g) * RST + kof;
                bh[n][0]   = __float_as_uint(Whi[rb]);
                bh[n][1]   = __float_as_uint(Whi[rb + 4]);
                bmid[n][0] = __float_as_uint(Wmid[rb]);
                bmid[n][1] = __float_as_uint(Wmid[rb + 4]);
            }
#pragma unroll
            for (int j = 0; j < 2; j++)
#pragma unroll
                for (int n = 0; n < 8; n++) {
                    mma_tf32(acc[j][n], ah[j], bh[n]);
                    mma_tf32(acc[j][n], ah[j], bmid[n]);
                    mma_tf32(acc[j][n], am[j], bh[n]);
                }
        }
        __syncthreads();
    }

    const int cr = g;
    const int cn = cfrag * 2;
#pragma unroll
    for (int n = 0; n < 8; n++) {
        int ncol = bn + wn + n * 8 + cn;
        float bx = __ldg(b1 + ncol)     + (b2 ? __ldg(b2 + ncol)     : 0.0f);
        float by = __ldg(b1 + ncol + 1) + (b2 ? __ldg(b2 + ncol + 1) : 0.0f);
#pragma unroll
        for (int j = 0; j < 2; j++) {
            int m0 = bm + wm + j * 16 + cr;
#pragma unroll
            for (int h = 0; h < 2; h++) {
                int m = m0 + h * 8;
                size_t crow = cmode
                    ? ((size_t)(m & 31) * Tlen + (size_t)(m >> 5)) * (size_t)Ntot
                    : (size_t)m * Ntot;
                float2 v;
                v.x = acc[j][n][h * 2 + 0] + bx;
                v.y = acc[j][n][h * 2 + 1] + by;
                *(float2*)&C[crow + ncol] = v;
            }
        }
    }
}

// =============================================================================
// persistent recurrent kernel — VERBATIM from the round-8 passing kernel
// (best measured configuration: 128 CTAs, 4 h-dims each, W hi/mid pre-split
// in registers, per-warp counter spin, threadfence+atomicAdd publish).
// =============================================================================
__global__ __launch_bounds__(RTHREADS) void lstm_rec_mma(
    const float* __restrict__ G, const float* __restrict__ Wh,
    float* __restrict__ hkb, float* __restrict__ hseq,
    int* __restrict__ cnt)
{
    extern __shared__ float sm[];
    float* hsh = sm;                    // [512][RSH]  h(t-1), k-major
    float* red = sm + 512 * RSH;        // [8][16*RSH] per-warp partials
    float* csh = red + 8 * 16 * RSH;    // [128] cell state (dd*32+b)

    const int tid  = threadIdx.x;
    const int lane = tid & 31;
    const int kk   = tid >> 5;          // warp = k-chunk 0..7
    const int g    = lane >> 2;         // frag row group 0..7
    const int cf   = lane & 3;          // frag col 0..3
    const int d0   = blockIdx.x * 4;

    // ---- load W fragments for this warp's k-chunk into registers (hi/mid) ---
    uint32_t wh[8][4], wmd[8][4];
    {
        const int j0 = g, j1 = g + 8;
        const float* r0 = Wh + ((size_t)(j0 >> 2) * Hdim + d0 + (j0 & 3)) * Hdim;
        const float* r1 = Wh + ((size_t)(j1 >> 2) * Hdim + d0 + (j1 & 3)) * Hdim;
#pragma unroll
        for (int s = 0; s < 8; s++) {
            int k = kk * 64 + s * 8 + cf;
            float w0 = __ldg(r0 + k);
            float w1 = __ldg(r1 + k);
            float w2 = __ldg(r0 + k + 4);
            float w3 = __ldg(r1 + k + 4);
            wh[s][0] = f2tf32(w0); wmd[s][0] = f2tf32(w0 - __uint_as_float(wh[s][0]));
            wh[s][1] = f2tf32(w1); wmd[s][1] = f2tf32(w1 - __uint_as_float(wh[s][1]));
            wh[s][2] = f2tf32(w2); wmd[s][2] = f2tf32(w2 - __uint_as_float(wh[s][2]));
            wh[s][3] = f2tf32(w3); wmd[s][3] = f2tf32(w3 - __uint_as_float(wh[s][3]));
        }
    }
    if (tid < 128) csh[tid] = 0.0f;
    __syncthreads();

    const int dd = tid >> 5;            // activation role (tid<128)
    const int b  = tid & 31;

    for (int t = 0; t < Tlen; t++) {
        // prefetch this step's gate pre-activations (independent of h)
        float gp0 = 0.f, gp1 = 0.f, gp2 = 0.f, gp3 = 0.f;
        if (tid < 128) {
            const float* gb = G + ((size_t)t * Bsz + b) * G4 + d0 + dd;
            gp0 = __ldg(gb);
            gp1 = __ldg(gb + Hdim);
            gp2 = __ldg(gb + 2 * Hdim);
            gp3 = __ldg(gb + 3 * Hdim);
        }
        if (t > 0) {
            // per-warp wait for full h(t-1)
            if (lane == 0) {
                volatile int* vc = cnt;
                while (vc[t - 1] < NCTA) {}
            }
            __syncwarp();
            asm volatile("" ::: "memory");
            // warp loads its own k-chunk of h(t-1): rows kk*64..kk*64+63
            const float4* src = (const float4*)(hkb + (size_t)(t - 1) * Hdim * Bsz
                                                + (size_t)kk * 64 * Bsz);
#pragma unroll
            for (int r = 0; r < 16; r++) {
                int f = lane + r * 32;          // float4 index 0..511 in chunk
                float4 v = __ldcg(src + f);
                int k = f >> 3, bg = f & 7;
                *(float4*)&hsh[(kk * 64 + k) * RSH + bg * 4] = v;
            }
            __syncwarp();

            // compute partial[16x32] = Wchunk @ hchunk (3-pass tf32)
            float acc[4][4];
#pragma unroll
            for (int nt = 0; nt < 4; nt++)
#pragma unroll
                for (int q = 0; q < 4; q++) acc[nt][q] = 0.0f;

#pragma unroll
            for (int s = 0; s < 8; s++) {
                const int krow = kk * 64 + s * 8;
                uint32_t hh[4][2], hm[4][2];
#pragma unroll
                for (int nt = 0; nt < 4; nt++) {
                    float v0 = hsh[(krow + cf) * RSH + nt * 8 + g];
                    float v1 = hsh[(krow + cf + 4) * RSH + nt * 8 + g];
                    hh[nt][0] = f2tf32(v0); hm[nt][0] = f2tf32(v0 - __uint_as_float(hh[nt][0]));
                    hh[nt][1] = f2tf32(v1); hm[nt][1] = f2tf32(v1 - __uint_as_float(hh[nt][1]));
                }
#pragma unroll
                for (int nt = 0; nt < 4; nt++) {
                    mma_tf32(acc[nt], wh[s], hh[nt]);   // hi*hi
                    mma_tf32(acc[nt], wh[s], hm[nt]);   // hi*mid
                    mma_tf32(acc[nt], wmd[s], hh[nt]);  // mid*hi
                }
            }
            // store partials: C frag row g/g+8, col 2cf/2cf+1 within tile nt
            float* rp = red + kk * 16 * RSH;
#pragma unroll
            for (int nt = 0; nt < 4; nt++) {
                int bcol = nt * 8 + cf * 2;
                float2 lo = { acc[nt][0], acc[nt][1] };
                float2 hi = { acc[nt][2], acc[nt][3] };
                *(float2*)&rp[g * RSH + bcol]       = lo;
                *(float2*)&rp[(g + 8) * RSH + bcol] = hi;
            }
        }
        __syncthreads();

        if (tid < 128) {
            float s0 = gp0, s1 = gp1, s2 = gp2, s3 = gp3;
            if (t > 0) {
                int o0 = (0 * 4 + dd) * RSH + b;
                int o1 = (1 * 4 + dd) * RSH + b;
                int o2 = (2 * 4 + dd) * RSH + b;
                int o3 = (3 * 4 + dd) * RSH + b;
#pragma unroll
                for (int w = 0; w < 8; w++) {
                    const float* rw = red + w * 16 * RSH;
                    s0 += rw[o0];
                    s1 += rw[o1];
                    s2 += rw[o2];
                    s3 += rw[o3];
                }
            }
            float ig = sigm_(s0);
            float fg = sigm_(s1);
            float gg = tanh_(s2);
            float og = sigm_(s3);
            float cv = fg * csh[tid] + ig * gg;
            csh[tid] = cv;
            float hv = og * tanh_(cv);
            hkb[(size_t)t * Hdim * Bsz + (size_t)(d0 + dd) * Bsz + b] = hv;
            hseq[((size_t)t * Bsz + b) * Hdim + d0 + dd] = hv;
        }
        __threadfence();
        __syncthreads();
        if (tid == 0) atomicAdd(&cnt[t], 1);
    }
}

// ---------------- launcher ---------------------------------------------------
extern "C" void kernel_launch(void* const* d_in, const int* in_sizes, int n_in,
                              void* d_out, int out_size)
{
    (void)in_sizes; (void)n_in; (void)out_size;
    const float* x     = (const float*)d_in[0];
    const float* W_ih  = (const float*)d_in[1];   // [2][2048][512]
    const float* W_hh  = (const float*)d_in[2];   // [2][2048][512]
    const float* b_ih  = (const float*)d_in[3];   // [2][2048]
    const float* b_hh  = (const float*)d_in[4];   // [2][2048]
    const float* W_out = (const float*)d_in[5];   // [512][512]
    const float* b_out = (const float*)d_in[6];   // [512]
    float* out = (float*)d_out;

    float *G, *h1, *h2, *hkb; int* cnt;
    cudaGetSymbolAddress((void**)&G,   g_G);
    cudaGetSymbolAddress((void**)&h1,  g_h1);
    cudaGetSymbolAddress((void**)&h2,  g_h2);
    cudaGetSymbolAddress((void**)&hkb, g_hkb);
    cudaGetSymbolAddress((void**)&cnt, g_cnt);

    const int rec_smem  = (512 * RSH + 8 * 16 * RSH + 128) * 4;  // 102912 B
    const int gemm_smem = 2 * BUF_BYTES;                         // 147456 B
    cudaFuncSetAttribute(lstm_rec_mma, cudaFuncAttributeMaxDynamicSharedMemorySize, rec_smem);
    cudaFuncSetAttribute(gemm_tf32, cudaFuncAttributeMaxDynamicSharedMemorySize, gemm_smem);

    zero_cnt_kernel<<<8, 256>>>();

    // layer 0: gates = x @ Wih0^T + b
    gemm_tf32<<<dim3(G4 / TN, Mrows / TM), 256, gemm_smem>>>(
        x, W_ih, b_ih, b_hh, G, G4, /*amode=*/0, /*cmode=*/0);
    lstm_rec_mma<<<NCTA, RTHREADS, rec_smem>>>(G, W_hh, hkb, h1, cnt);

    // layer 1
    const size_t wl = (size_t)G4 * Hdim;
    gemm_tf32<<<dim3(G4 / TN, Mrows / TM), 256, gemm_smem>>>(
        h1, W_ih + wl, b_ih + G4, b_hh + G4, G, G4, /*amode=*/1, /*cmode=*/0);
    lstm_rec_mma<<<NCTA, RTHREADS, rec_smem>>>(G, W_hh + wl, hkb, h2, cnt + Tlen);

    // output projection -> [B,T,H]
    gemm_tf32<<<dim3(Hdim / TN, Mrows / TM), 256, gemm_smem>>>(
        h2, W_out, b_out, nullptr, out, Hdim, /*amode=*/1, /*cmode=*/1);
}

// round 15
// speedup vs baseline: 1.2919x; 1.0008x over previous
#include <cuda_runtime.h>
#include <cstdint>
#include <cstddef>

// Problem constants
#define Bsz   32
#define Tlen  1024
#define Hdim  512
#define G4    2048                 // 4*H
#define Mrows (Tlen * Bsz)         // 32768
#define NCTA  128                  // recurrent CTAs
#define RTHREADS 256
#define RSH 40                     // rec smem row stride in floats (160 B)

// ---------------- static device scratch (no allocations allowed) -------------
__device__ float g_G[(size_t)Mrows * G4];          // gate pre-activations [t*B+b][4H]
__device__ float g_h1[(size_t)Mrows * Hdim];       // layer-0 outputs [t*B+b][H]
__device__ float g_h2[(size_t)Mrows * Hdim];       // layer-1 outputs [t*B+b][H]
__device__ float g_hkb[(size_t)Tlen * Hdim * Bsz]; // h in [t][k][b] layout
__device__ int   g_cnt[2][Tlen];                   // per-step arrival counters

// ---------------- helpers ----------------------------------------------------
__device__ __forceinline__ float sigm_(float x) { return 1.0f / (1.0f + __expf(-x)); }
__device__ __forceinline__ float tanh_(float x) {
    float y;
    asm("tanh.approx.f32 %0, %1;" : "=f"(y) : "f"(x));
    return y;
}
__device__ __forceinline__ uint32_t f2tf32(float x) {
    uint32_t r;
    asm("cvt.rna.tf32.f32 %0, %1;" : "=r"(r) : "f"(x));
    return r;
}
__device__ __forceinline__ void mma_tf32(float* c, const uint32_t* a, const uint32_t* b) {
    asm volatile("mma.sync.aligned.m16n8k8.row.col.f32.tf32.tf32.f32 "
                 "{%0,%1,%2,%3}, {%4,%5,%6,%7}, {%8,%9}, {%0,%1,%2,%3};"
                 : "+f"(c[0]), "+f"(c[1]), "+f"(c[2]), "+f"(c[3])
                 : "r"(a[0]), "r"(a[1]), "r"(a[2]), "r"(a[3]), "r"(b[0]), "r"(b[1]));
}

// ---------------- counter reset (graph-replay safe) --------------------------
__global__ void zero_cnt_kernel() {
    int i = blockIdx.x * blockDim.x + threadIdx.x;
    if (i < 2 * Tlen) ((int*)g_cnt)[i] = 0;
}

// =============================================================================
// tf32 mma.sync 3-pass split GEMM v2:  C[m][n] = sum_k A[m][k]*W[n][k] + bias
// Same math as the round-7/8 passing kernel, but the hi/mid tf32 split is done
// ONCE at staging time (4 smem tiles: Ahi/Amid/Whi/Wmid) instead of at every
// fragment load. Compute loop = raw-bit LDS + mma only (no ALU).
// amode 0: A row m -> x[(m&31)*T + (m>>5)]   (x is [B,T,H])
// amode 1: A row m -> A[m]
// cmode 0: C row m -> C[m*Ntot]
// cmode 1: C row m -> C[((m&31)*T + (m>>5))*Ntot]
// =============================================================================
#define TM 128
#define TN 128
#define KS 32
#define RST 36                     // smem row stride in floats (144 B)
#define MAT_F (128 * RST)          // 4608 floats per tile
#define BUF_F (4 * MAT_F)          // Ahi + Amid + Whi + Wmid
#define OFF_AHI  0
#define OFF_AMID (1 * MAT_F)
#define OFF_WHI  (2 * MAT_F)
#define OFF_WMID (3 * MAT_F)
#define BUF_BYTES (BUF_F * 4)      // 73728 B per stage buffer

__global__ __launch_bounds__(256, 1) void gemm_tf32(
    const float* __restrict__ A, const float* __restrict__ W,
    const float* __restrict__ b1, const float* __restrict__ b2,
    float* __restrict__ C, int Ntot, int amode, int cmode)
{
    extern __shared__ float smf[];

    const int tid  = threadIdx.x;
    const int wid  = tid >> 5;
    const int lane = tid & 31;
    const int bm = blockIdx.y * TM;
    const int bn = blockIdx.x * TN;
    const int wm = (wid & 3) * 32;
    const int wn = (wid >> 2) * 64;
    const int g  = lane >> 2;
    const int cfrag = lane & 3;

    const int rr  = tid >> 1;
    const int cc0 = (tid & 1) * 16;
    size_t arow;
    {
        int m = bm + rr;
        arow = amode ? (size_t)m * Hdim
                     : ((size_t)(m & 31) * Tlen + (size_t)(m >> 5)) * Hdim;
    }
    const float* ap = A + arow;
    const float* wp = W + (size_t)(bn + rr) * Hdim;
    const int sts = rr * RST + cc0;

    float acc[2][8][4];
#pragma unroll
    for (int i = 0; i < 2; i++)
#pragma unroll
        for (int j = 0; j < 8; j++)
#pragma unroll
            for (int q = 0; q < 4; q++) acc[i][j][q] = 0.0f;

    float4 pa[4], pw[4];
#pragma unroll
    for (int i = 0; i < 4; i++) {
        pa[i] = __ldg((const float4*)(ap + cc0 + i * 4));
        pw[i] = __ldg((const float4*)(wp + cc0 + i * 4));
    }

    const int NSTG = Hdim / KS;  // 16
    for (int kt = 0; kt < NSTG; kt++) {
        float* buf = smf + (kt & 1) * BUF_F;
        // ---- stage with one-time hi/mid split ----
#pragma unroll
        for (int i = 0; i < 4; i++) {
            float4 v = pa[i];
            float4 hi, mid;
            hi.x = __uint_as_float(f2tf32(v.x)); mid.x = __uint_as_float(f2tf32(v.x - hi.x));
            hi.y = __uint_as_float(f2tf32(v.y)); mid.y = __uint_as_float(f2tf32(v.y - hi.y));
            hi.z = __uint_as_float(f2tf32(v.z)); mid.z = __uint_as_float(f2tf32(v.z - hi.z));
            hi.w = __uint_as_float(f2tf32(v.w)); mid.w = __uint_as_float(f2tf32(v.w - hi.w));
            *(float4*)&buf[OFF_AHI  + sts + i * 4] = hi;
            *(float4*)&buf[OFF_AMID + sts + i * 4] = mid;

            v = pw[i];
            hi.x = __uint_as_float(f2tf32(v.x)); mid.x = __uint_as_float(f2tf32(v.x - hi.x));
            hi.y = __uint_as_float(f2tf32(v.y)); mid.y = __uint_as_float(f2tf32(v.y - hi.y));
            hi.z = __uint_as_float(f2tf32(v.z)); mid.z = __uint_as_float(f2tf32(v.z - hi.z));
            hi.w = __uint_as_float(f2tf32(v.w)); mid.w = __uint_as_float(f2tf32(v.w - hi.w));
            *(float4*)&buf[OFF_WHI  + sts + i * 4] = hi;
            *(float4*)&buf[OFF_WMID + sts + i * 4] = mid;
        }
        __syncthreads();

        if (kt + 1 < NSTG) {
            int kb = (kt + 1) * KS + cc0;
#pragma unroll
            for (int i = 0; i < 4; i++) {
                pa[i] = __ldg((const float4*)(ap + kb + i * 4));
                pw[i] = __ldg((const float4*)(wp + kb + i * 4));
            }
        }

        const float* Ahi  = buf + OFF_AHI;
        const float* Amid = buf + OFF_AMID;
        const float* Whi  = buf + OFF_WHI;
        const float* Wmid = buf + OFF_WMID;
        // ---- compute: raw-bit fragment loads + mma only ----
#pragma unroll
        for (int ks = 0; ks < 4; ks++) {
            const int kof = ks * 8 + cfrag;
            uint32_t ah[2][4], am[2][4];
#pragma unroll
            for (int j = 0; j < 2; j++) {
                int ra = (wm + j * 16 + g) * RST + kof;
                ah[j][0] = __float_as_uint(Ahi[ra]);
                ah[j][1] = __float_as_uint(Ahi[ra + 8 * RST]);
                ah[j][2] = __float_as_uint(Ahi[ra + 4]);
                ah[j][3] = __float_as_uint(Ahi[ra + 8 * RST + 4]);
                am[j][0] = __float_as_uint(Amid[ra]);
                am[j][1] = __float_as_uint(Amid[ra + 8 * RST]);
                am[j][2] = __float_as_uint(Amid[ra + 4]);
                am[j][3] = __float_as_uint(Amid[ra + 8 * RST + 4]);
            }
            uint32_t bh[8][2], bmid[8][2];
#pragma unroll
            for (int n = 0; n < 8; n++) {
                int rb = (wn + n * 8 + g) * RST + kof;
                bh[n][0]   = __float_as_uint(Whi[rb]);
                bh[n][1]   = __float_as_uint(Whi[rb + 4]);
                bmid[n][0] = __float_as_uint(Wmid[rb]);
                bmid[n][1] = __float_as_uint(Wmid[rb + 4]);
            }
#pragma unroll
            for (int j = 0; j < 2; j++)
#pragma unroll
                for (int n = 0; n < 8; n++) {
                    mma_tf32(acc[j][n], ah[j], bh[n]);
                    mma_tf32(acc[j][n], ah[j], bmid[n]);
                    mma_tf32(acc[j][n], am[j], bh[n]);
                }
        }
        __syncthreads();
    }

    const int cr = g;
    const int cn = cfrag * 2;
#pragma unroll
    for (int n = 0; n < 8; n++) {
        int ncol = bn + wn + n * 8 + cn;
        float bx = __ldg(b1 + ncol)     + (b2 ? __ldg(b2 + ncol)     : 0.0f);
        float by = __ldg(b1 + ncol + 1) + (b2 ? __ldg(b2 + ncol + 1) : 0.0f);
#pragma unroll
        for (int j = 0; j < 2; j++) {
            int m0 = bm + wm + j * 16 + cr;
#pragma unroll
            for (int h = 0; h < 2; h++) {
                int m = m0 + h * 8;
                size_t crow = cmode
                    ? ((size_t)(m & 31) * Tlen + (size_t)(m >> 5)) * (size_t)Ntot
                    : (size_t)m * Ntot;
                float2 v;
                v.x = acc[j][n][h * 2 + 0] + bx;
                v.y = acc[j][n][h * 2 + 1] + by;
                *(float2*)&C[crow + ncol] = v;
            }
        }
    }
}

// =============================================================================
// persistent recurrent kernel — VERBATIM from the round-8 passing kernel
// (best measured configuration: 128 CTAs, 4 h-dims each, W hi/mid pre-split
// in registers, per-warp counter spin, threadfence+atomicAdd publish).
// =============================================================================
__global__ __launch_bounds__(RTHREADS) void lstm_rec_mma(
    const float* __restrict__ G, const float* __restrict__ Wh,
    float* __restrict__ hkb, float* __restrict__ hseq,
    int* __restrict__ cnt)
{
    extern __shared__ float sm[];
    float* hsh = sm;                    // [512][RSH]  h(t-1), k-major
    float* red = sm + 512 * RSH;        // [8][16*RSH] per-warp partials
    float* csh = red + 8 * 16 * RSH;    // [128] cell state (dd*32+b)

    const int tid  = threadIdx.x;
    const int lane = tid & 31;
    const int kk   = tid >> 5;          // warp = k-chunk 0..7
    const int g    = lane >> 2;         // frag row group 0..7
    const int cf   = lane & 3;          // frag col 0..3
    const int d0   = blockIdx.x * 4;

    // ---- load W fragments for this warp's k-chunk into registers (hi/mid) ---
    uint32_t wh[8][4], wmd[8][4];
    {
        const int j0 = g, j1 = g + 8;
        const float* r0 = Wh + ((size_t)(j0 >> 2) * Hdim + d0 + (j0 & 3)) * Hdim;
        const float* r1 = Wh + ((size_t)(j1 >> 2) * Hdim + d0 + (j1 & 3)) * Hdim;
#pragma unroll
        for (int s = 0; s < 8; s++) {
            int k = kk * 64 + s * 8 + cf;
            float w0 = __ldg(r0 + k);
            float w1 = __ldg(r1 + k);
            float w2 = __ldg(r0 + k + 4);
            float w3 = __ldg(r1 + k + 4);
            wh[s][0] = f2tf32(w0); wmd[s][0] = f2tf32(w0 - __uint_as_float(wh[s][0]));
            wh[s][1] = f2tf32(w1); wmd[s][1] = f2tf32(w1 - __uint_as_float(wh[s][1]));
            wh[s][2] = f2tf32(w2); wmd[s][2] = f2tf32(w2 - __uint_as_float(wh[s][2]));
            wh[s][3] = f2tf32(w3); wmd[s][3] = f2tf32(w3 - __uint_as_float(wh[s][3]));
        }
    }
    if (tid < 128) csh[tid] = 0.0f;
    __syncthreads();

    const int dd = tid >> 5;            // activation role (tid<128)
    const int b  = tid & 31;

    for (int t = 0; t < Tlen; t++) {
        // prefetch this step's gate pre-activations (independent of h)
        float gp0 = 0.f, gp1 = 0.f, gp2 = 0.f, gp3 = 0.f;
        if (tid < 128) {
            const float* gb = G + ((size_t)t * Bsz + b) * G4 + d0 + dd;
            gp0 = __ldg(gb);
            gp1 = __ldg(gb + Hdim);
            gp2 = __ldg(gb + 2 * Hdim);
            gp3 = __ldg(gb + 3 * Hdim);
        }
        if (t > 0) {
            // per-warp wait for full h(t-1)
            if (lane == 0) {
                volatile int* vc = cnt;
                while (vc[t - 1] < NCTA) {}
            }
            __syncwarp();
            asm volatile("" ::: "memory");
            // warp loads its own k-chunk of h(t-1): rows kk*64..kk*64+63
            const float4* src = (const float4*)(hkb + (size_t)(t - 1) * Hdim * Bsz
                                                + (size_t)kk * 64 * Bsz);
#pragma unroll
            for (int r = 0; r < 16; r++) {
                int f = lane + r * 32;          // float4 index 0..511 in chunk
                float4 v = __ldcg(src + f);
                int k = f >> 3, bg = f & 7;
                *(float4*)&hsh[(kk * 64 + k) * RSH + bg * 4] = v;
            }
            __syncwarp();

            // compute partial[16x32] = Wchunk @ hchunk (3-pass tf32)
            float acc[4][4];
#pragma unroll
            for (int nt = 0; nt < 4; nt++)
#pragma unroll
                for (int q = 0; q < 4; q++) acc[nt][q] = 0.0f;

#pragma unroll
            for (int s = 0; s < 8; s++) {
                const int krow = kk * 64 + s * 8;
                uint32_t hh[4][2], hm[4][2];
#pragma unroll
                for (int nt = 0; nt < 4; nt++) {
                    float v0 = hsh[(krow + cf) * RSH + nt * 8 + g];
                    float v1 = hsh[(krow + cf + 4) * RSH + nt * 8 + g];
                    hh[nt][0] = f2tf32(v0); hm[nt][0] = f2tf32(v0 - __uint_as_float(hh[nt][0]));
                    hh[nt][1] = f2tf32(v1); hm[nt][1] = f2tf32(v1 - __uint_as_float(hh[nt][1]));
                }
#pragma unroll
                for (int nt = 0; nt < 4; nt++) {
                    mma_tf32(acc[nt], wh[s], hh[nt]);   // hi*hi
                    mma_tf32(acc[nt], wh[s], hm[nt]);   // hi*mid
                    mma_tf32(acc[nt], wmd[s], hh[nt]);  // mid*hi
                }
            }
            // store partials: C frag row g/g+8, col 2cf/2cf+1 within tile nt
            float* rp = red + kk * 16 * RSH;
#pragma unroll
            for (int nt = 0; nt < 4; nt++) {
                int bcol = nt * 8 + cf * 2;
                float2 lo = { acc[nt][0], acc[nt][1] };
                float2 hi = { acc[nt][2], acc[nt][3] };
                *(float2*)&rp[g * RSH + bcol]       = lo;
                *(float2*)&rp[(g + 8) * RSH + bcol] = hi;
            }
        }
        __syncthreads();

        if (tid < 128) {
            float s0 = gp0, s1 = gp1, s2 = gp2, s3 = gp3;
            if (t > 0) {
                int o0 = (0 * 4 + dd) * RSH + b;
                int o1 = (1 * 4 + dd) * RSH + b;
                int o2 = (2 * 4 + dd) * RSH + b;
                int o3 = (3 * 4 + dd) * RSH + b;
#pragma unroll
                for (int w = 0; w < 8; w++) {
                    const float* rw = red + w * 16 * RSH;
                    s0 += rw[o0];
                    s1 += rw[o1];
                    s2 += rw[o2];
                    s3 += rw[o3];
                }
            }
            float ig = sigm_(s0);
            float fg = sigm_(s1);
            float gg = tanh_(s2);
            float og = sigm_(s3);
            float cv = fg * csh[tid] + ig * gg;
            csh[tid] = cv;
            float hv = og * tanh_(cv);
            hkb[(size_t)t * Hdim * Bsz + (size_t)(d0 + dd) * Bsz + b] = hv;
            hseq[((size_t)t * Bsz + b) * Hdim + d0 + dd] = hv;
        }
        __threadfence();
        __syncthreads();
        if (tid == 0) atomicAdd(&cnt[t], 1);
    }
}

// ---------------- launcher ---------------------------------------------------
extern "C" void kernel_launch(void* const* d_in, const int* in_sizes, int n_in,
                              void* d_out, int out_size)
{
    (void)in_sizes; (void)n_in; (void)out_size;
    const float* x     = (const float*)d_in[0];
    const float* W_ih  = (const float*)d_in[1];   // [2][2048][512]
    const float* W_hh  = (const float*)d_in[2];   // [2][2048][512]
    const float* b_ih  = (const float*)d_in[3];   // [2][2048]
    const float* b_hh  = (const float*)d_in[4];   // [2][2048]
    const float* W_out = (const float*)d_in[5];   // [512][512]
    const float* b_out = (const float*)d_in[6];   // [512]
    float* out = (float*)d_out;

    float *G, *h1, *h2, *hkb; int* cnt;
    cudaGetSymbolAddress((void**)&G,   g_G);
    cudaGetSymbolAddress((void**)&h1,  g_h1);
    cudaGetSymbolAddress((void**)&h2,  g_h2);
    cudaGetSymbolAddress((void**)&hkb, g_hkb);
    cudaGetSymbolAddress((void**)&cnt, g_cnt);

    const int rec_smem  = (512 * RSH + 8 * 16 * RSH + 128) * 4;  // 102912 B
    const int gemm_smem = 2 * BUF_BYTES;                         // 147456 B
    cudaFuncSetAttribute(lstm_rec_mma, cudaFuncAttributeMaxDynamicSharedMemorySize, rec_smem);
    cudaFuncSetAttribute(gemm_tf32, cudaFuncAttributeMaxDynamicSharedMemorySize, gemm_smem);

    zero_cnt_kernel<<<8, 256>>>();

    // layer 0: gates = x @ Wih0^T + b
    gemm_tf32<<<dim3(G4 / TN, Mrows / TM), 256, gemm_smem>>>(
        x, W_ih, b_ih, b_hh, G, G4, /*amode=*/0, /*cmode=*/0);
    lstm_rec_mma<<<NCTA, RTHREADS, rec_smem>>>(G, W_hh, hkb, h1, cnt);

    // layer 1
    const size_t wl = (size_t)G4 * Hdim;
    gemm_tf32<<<dim3(G4 / TN, Mrows / TM), 256, gemm_smem>>>(
        h1, W_ih + wl, b_ih + G4, b_hh + G4, G, G4, /*amode=*/1, /*cmode=*/0);
    lstm_rec_mma<<<NCTA, RTHREADS, rec_smem>>>(G, W_hh + wl, hkb, h2, cnt + Tlen);

    // output projection -> [B,T,H]
    gemm_tf32<<<dim3(Hdim / TN, Mrows / TM), 256, gemm_smem>>>(
        h2, W_out, b_out, nullptr, out, Hdim, /*amode=*/1, /*cmode=*/1);
}